// round 3
// baseline (speedup 1.0000x reference)
#include <cuda_runtime.h>

// TopkWeightClusterLoss: loss = COEFF/(TOPK-1) * sum over all elements of
//   sum_{i in top4 of d2} d2_i * (1 - softmax(top4)_i)
// where d2 are squared distances of w to centers q*s, q in [-7..7].
// Convexity of d2 in q => top-4 candidates are q in {+-4,+-5,+-6,+-7} only.

#define ROWS 4096
#define COLS 4096
#define THREADS 256

__device__ float g_row_partial[ROWS];

__device__ __forceinline__ void cswap_desc(float& a, float& b) {
    float lo = fminf(a, b);
    a = fmaxf(a, b);
    b = lo;
}

__device__ __forceinline__ float elem_loss(float x, float c4, float c5, float c6, float c7) {
    // Left-end candidates: centers -7s..-4s -> d = x + q*s
    float l0 = x + c7; l0 *= l0;
    float l1 = x + c6; l1 *= l1;
    float l2 = x + c5; l2 *= l2;
    float l3 = x + c4; l3 *= l3;
    // Right-end candidates: centers +4s..+7s
    float r0 = x - c7; r0 *= r0;
    float r1 = x - c6; r1 *= r1;
    float r2 = x - c5; r2 *= r2;
    float r3 = x - c4; r3 *= r3;

    // Sort each group of 4 descending (5-comparator network).
    cswap_desc(l0, l1); cswap_desc(l2, l3); cswap_desc(l0, l2); cswap_desc(l1, l3); cswap_desc(l1, l2);
    cswap_desc(r0, r1); cswap_desc(r2, r3); cswap_desc(r0, r2); cswap_desc(r1, r3); cswap_desc(r1, r2);

    // Bitonic half-cleaner: top-4 multiset of the 8 candidates.
    float m0 = fmaxf(l0, r3);
    float m1 = fmaxf(l1, r2);
    float m2 = fmaxf(l2, r1);
    float m3 = fmaxf(l3, r0);

    // softmax over {m0..m3}; loss term = S - dot(m, e)/E
    float mx = fmaxf(fmaxf(m0, m1), fmaxf(m2, m3));
    float e0 = __expf(m0 - mx);
    float e1 = __expf(m1 - mx);
    float e2 = __expf(m2 - mx);
    float e3 = __expf(m3 - mx);
    float E = (e0 + e1) + (e2 + e3);
    float S = (m0 + m1) + (m2 + m3);
    float D = m0 * e0 + m1 * e1 + m2 * e2 + m3 * e3;
    return S - __fdividef(D, E);
}

__global__ __launch_bounds__(THREADS) void topk_loss_rows(
    const float* __restrict__ weight, const float* __restrict__ scale)
{
    const int row = blockIdx.x;
    const float s = __ldg(&scale[row]);
    const float c4 = 4.0f * s, c5 = 5.0f * s, c6 = 6.0f * s, c7 = 7.0f * s;

    const float4* wrow = reinterpret_cast<const float4*>(weight + (size_t)row * COLS);

    float acc = 0.0f;
#pragma unroll
    for (int it = 0; it < COLS / 4 / THREADS; ++it) {
        float4 v = wrow[it * THREADS + threadIdx.x];
        acc += elem_loss(v.x, c4, c5, c6, c7);
        acc += elem_loss(v.y, c4, c5, c6, c7);
        acc += elem_loss(v.z, c4, c5, c6, c7);
        acc += elem_loss(v.w, c4, c5, c6, c7);
    }

    // Deterministic block reduction.
    __shared__ float red[THREADS / 32];
#pragma unroll
    for (int off = 16; off; off >>= 1)
        acc += __shfl_xor_sync(0xffffffffu, acc, off);
    if ((threadIdx.x & 31) == 0) red[threadIdx.x >> 5] = acc;
    __syncthreads();
    if (threadIdx.x < 32) {
        float v = (threadIdx.x < THREADS / 32) ? red[threadIdx.x] : 0.0f;
#pragma unroll
        for (int off = 16; off; off >>= 1)
            v += __shfl_xor_sync(0xffffffffu, v, off);
        if (threadIdx.x == 0) g_row_partial[row] = v;
    }
}

__global__ __launch_bounds__(1024) void topk_loss_reduce(float* __restrict__ out)
{
    __shared__ float red[32];
    float acc = 0.0f;
    for (int i = threadIdx.x; i < ROWS; i += 1024)
        acc += g_row_partial[i];
#pragma unroll
    for (int off = 16; off; off >>= 1)
        acc += __shfl_xor_sync(0xffffffffu, acc, off);
    if ((threadIdx.x & 31) == 0) red[threadIdx.x >> 5] = acc;
    __syncthreads();
    if (threadIdx.x < 32) {
        float v = (threadIdx.x < 32) ? red[threadIdx.x] : 0.0f;
#pragma unroll
        for (int off = 16; off; off >>= 1)
            v += __shfl_xor_sync(0xffffffffu, v, off);
        if (threadIdx.x == 0) out[0] = v * (0.01f / 3.0f);  // COEFF / (TOPK-1)
    }
}

extern "C" void kernel_launch(void* const* d_in, const int* in_sizes, int n_in,
                              void* d_out, int out_size)
{
    const float* weight = (const float*)d_in[0];
    const float* scale  = (const float*)d_in[1];
    float* out = (float*)d_out;

    topk_loss_rows<<<ROWS, THREADS>>>(weight, scale);
    topk_loss_reduce<<<1, 1024>>>(out);
}

// round 4
// speedup vs baseline: 1.6516x; 1.6516x over previous
#include <cuda_runtime.h>

// TopkWeightClusterLoss, algebraically reduced:
//   d2(q) = (x - q*s)^2 is convex in q => the 15-candidate sequence is V-shaped,
//   top-4 live at the outer q's. With y=|x| the top-4 multiset is exactly:
//     m0 = (y+7s)^2            (also the global max -> e0 = 1)
//     m1 = (y+6s)^2
//     m2 = (max(y+5s, 6s-y))^2
//     m3 = (max(y+4s, 7s-y))^2
//   loss_elem = S - D/E with e_i = exp(m_i - m0), E = 1+e1+e2+e3,
//   S = sum m_i, D = m0 + sum m_i*e_i.

#define ROWS 4096
#define COLS 4096
#define THREADS 256
#define L2E 1.4426950408889634f

__device__ float g_partial[ROWS];
__device__ unsigned int g_count = 0;

__device__ __forceinline__ float ex2f(float x) {
    float r; asm("ex2.approx.f32 %0, %1;" : "=f"(r) : "f"(x)); return r;
}
__device__ __forceinline__ float rcpf(float x) {
    float r; asm("rcp.approx.f32 %0, %1;" : "=f"(r) : "f"(x)); return r;
}

__device__ __forceinline__ float elem_loss(float x, float c4, float c5, float c6, float c7) {
    float y  = fabsf(x);
    float a0 = y + c7;
    float a1 = y + c6;
    float a2 = fmaxf(y + c5, c6 - y);
    float a3 = fmaxf(y + c4, c7 - y);
    float m0 = a0 * a0;
    float m1 = a1 * a1;
    float m2 = a2 * a2;
    float m3 = a3 * a3;
    float t  = -L2E * m0;                 // exp args: log2e*(m_i - m0)
    float e1 = ex2f(fmaf(m1, L2E, t));
    float e2 = ex2f(fmaf(m2, L2E, t));
    float e3 = ex2f(fmaf(m3, L2E, t));
    float E  = (1.0f + e1) + (e2 + e3);
    float S  = (m0 + m1) + (m2 + m3);
    float D  = fmaf(m3, e3, fmaf(m2, e2, fmaf(m1, e1, m0)));
    return fmaf(-D, rcpf(E), S);
}

__global__ __launch_bounds__(THREADS) void topk_loss_fused(
    const float* __restrict__ weight, const float* __restrict__ scale,
    float* __restrict__ out)
{
    const int row = blockIdx.x;
    const float s = __ldg(&scale[row]);
    const float c4 = 4.0f * s, c5 = 5.0f * s, c6 = 6.0f * s, c7 = 7.0f * s;

    const float4* wrow = reinterpret_cast<const float4*>(weight + (size_t)row * COLS);

    float acc = 0.0f;
#pragma unroll
    for (int it = 0; it < COLS / 4 / THREADS; ++it) {
        float4 v = wrow[it * THREADS + threadIdx.x];
        acc += elem_loss(v.x, c4, c5, c6, c7);
        acc += elem_loss(v.y, c4, c5, c6, c7);
        acc += elem_loss(v.z, c4, c5, c6, c7);
        acc += elem_loss(v.w, c4, c5, c6, c7);
    }

    // Deterministic block reduction.
    __shared__ float red[THREADS / 32];
    __shared__ bool s_last;
#pragma unroll
    for (int off = 16; off; off >>= 1)
        acc += __shfl_xor_sync(0xffffffffu, acc, off);
    if ((threadIdx.x & 31) == 0) red[threadIdx.x >> 5] = acc;
    __syncthreads();
    if (threadIdx.x == 0) {
        float v = 0.0f;
#pragma unroll
        for (int i = 0; i < THREADS / 32; ++i) v += red[i];
        g_partial[row] = v;
        __threadfence();
        unsigned int done = atomicAdd(&g_count, 1u);
        s_last = (done == (unsigned)(ROWS - 1));
    }
    __syncthreads();

    // Last block to finish performs the final (fixed-order => deterministic) reduce.
    if (s_last) {
        __threadfence();
        float a = 0.0f;
#pragma unroll
        for (int i = 0; i < ROWS / THREADS; ++i)
            a += g_partial[i * THREADS + threadIdx.x];
#pragma unroll
        for (int off = 16; off; off >>= 1)
            a += __shfl_xor_sync(0xffffffffu, a, off);
        if ((threadIdx.x & 31) == 0) red[threadIdx.x >> 5] = a;
        __syncthreads();
        if (threadIdx.x == 0) {
            float v = 0.0f;
#pragma unroll
            for (int i = 0; i < THREADS / 32; ++i) v += red[i];
            out[0] = v * (0.01f / 3.0f);   // COEFF / (TOPK-1)
            g_count = 0;                   // reset for next graph replay
        }
    }
}

extern "C" void kernel_launch(void* const* d_in, const int* in_sizes, int n_in,
                              void* d_out, int out_size)
{
    const float* weight = (const float*)d_in[0];
    const float* scale  = (const float*)d_in[1];
    float* out = (float*)d_out;

    topk_loss_fused<<<ROWS, THREADS>>>(weight, scale, out);
}